// round 1
// baseline (speedup 1.0000x reference)
#include <cuda_runtime.h>

#define Bb 8
#define Nn 2048
#define Kk 256
#define Ff 128
#define NCH 32
#define CSZ 64

// -------- scratch (device globals; no allocation allowed) --------
__device__ float g_Wh[Bb*Nn*Ff];
__device__ float g_u [Bb*Nn];
__device__ float g_v [Bb*Nn];
__device__ float g_key[Bb*Nn];      // sorted ascending keys = -v
__device__ int   g_perm[Bb*Nn];
__device__ float g_Ej [Bb*Nn];      // exp(v_sorted)
__device__ float g_Fj [Bb*Nn];      // exp(0.01*v_sorted)
__device__ float g_PzE[Bb*Nn];      // global inclusive scalar prefix of Ej
__device__ float g_PzF[Bb*Nn];
__device__ float g_PE [Bb*Nn*Ff];   // chunk-local inclusive prefixes
__device__ float g_PF [Bb*Nn*Ff];
__device__ float g_chE[Bb*NCH*Ff];
__device__ float g_chF[Bb*NCH*Ff];
__device__ float g_offE[Bb*NCH*Ff]; // exclusive chunk offsets
__device__ float g_offF[Bb*NCH*Ff];
__device__ float g_TF [Bb*Ff];      // total of F-branch vector sums

// ================= Kernel A: Wh = h@W, u = Wh.a_i, v = Wh.a_j =================
// block (32,8) = 256 thr, tile 64 rows x 128 cols, thread: 8 rows x 4 cols
#define KC 32
__global__ void gemm_uv(const float* __restrict__ h, const float* __restrict__ W,
                        const float* __restrict__ ai, const float* __restrict__ aj) {
    __shared__ float Ws[KC][Ff];    // 16KB
    __shared__ float hs[KC][68];    // [k][row 0..63], padded pitch (8.5KB)
    int tx = threadIdx.x;           // 0..31 -> cols 4tx..4tx+3
    int ty = threadIdx.y;           // 0..7  -> rows ty*8..ty*8+7
    int t  = ty*32 + tx;
    int b  = blockIdx.y;
    int row0 = blockIdx.x * 64;
    const float* hB = h + ((size_t)b*Nn + row0) * Kk;

    float acc[8][4];
    #pragma unroll
    for (int r=0;r<8;r++){ acc[r][0]=0.f; acc[r][1]=0.f; acc[r][2]=0.f; acc[r][3]=0.f; }

    for (int kc=0; kc<Kk; kc+=KC) {
        #pragma unroll
        for (int i=0;i<16;i++){                     // stage W chunk
            int idx = t + i*256;
            Ws[idx>>7][idx&127] = W[(size_t)(kc + (idx>>7))*Ff + (idx&127)];
        }
        #pragma unroll
        for (int i=0;i<8;i++){                      // stage h chunk (transposed)
            int idx = t + i*256;
            int kl = idx & (KC-1);
            int r  = idx >> 5;
            hs[kl][r] = hB[(size_t)r*Kk + kc + kl];
        }
        __syncthreads();
        #pragma unroll
        for (int kk=0; kk<KC; kk++){
            float4 w4 = *(const float4*)&Ws[kk][tx*4];
            float4 h0 = *(const float4*)&hs[kk][ty*8];
            float4 h1 = *(const float4*)&hs[kk][ty*8+4];
            float hv[8] = {h0.x,h0.y,h0.z,h0.w,h1.x,h1.y,h1.z,h1.w};
            #pragma unroll
            for (int r=0;r<8;r++){
                acc[r][0] = fmaf(hv[r], w4.x, acc[r][0]);
                acc[r][1] = fmaf(hv[r], w4.y, acc[r][1]);
                acc[r][2] = fmaf(hv[r], w4.z, acc[r][2]);
                acc[r][3] = fmaf(hv[r], w4.w, acc[r][3]);
            }
        }
        __syncthreads();
    }

    float4 ai4 = *(const float4*)&ai[tx*4];
    float4 aj4 = *(const float4*)&aj[tx*4];
    #pragma unroll
    for (int r=0;r<8;r++){
        int rg = row0 + ty*8 + r;
        float4 o; o.x=acc[r][0]; o.y=acc[r][1]; o.z=acc[r][2]; o.w=acc[r][3];
        *(float4*)&g_Wh[((size_t)b*Nn + rg)*Ff + tx*4] = o;
        float pu = o.x*ai4.x + o.y*ai4.y + o.z*ai4.z + o.w*ai4.w;
        float pv = o.x*aj4.x + o.y*aj4.y + o.z*aj4.z + o.w*aj4.w;
        #pragma unroll
        for (int s=16;s>0;s>>=1){
            pu += __shfl_xor_sync(0xffffffffu, pu, s);
            pv += __shfl_xor_sync(0xffffffffu, pv, s);
        }
        if (tx==0){ g_u[b*Nn+rg]=pu; g_v[b*Nn+rg]=pv; }
    }
}

// ================= Kernel B: per-batch bitonic sort on key=-v + scalar scans ==
__global__ void sort_scan() {
    __shared__ float skey[2048];
    __shared__ int   sidx[2048];
    __shared__ float sa[2048];
    __shared__ float sb[2048];
    __shared__ float st[2048];
    int b = blockIdx.x;
    int tid = threadIdx.x; // 1024

    for (int e=tid; e<2048; e+=1024){ skey[e] = -g_v[b*Nn+e]; sidx[e]=e; }
    __syncthreads();

    for (int k=2;k<=2048;k<<=1){
        for (int j=k>>1;j>0;j>>=1){
            for (int e=tid;e<2048;e+=1024){
                int ixj = e ^ j;
                if (ixj > e){
                    bool up = ((e & k) == 0);
                    float a=skey[e], c=skey[ixj];
                    if ((a > c) == up){
                        skey[e]=c; skey[ixj]=a;
                        int t1=sidx[e]; sidx[e]=sidx[ixj]; sidx[ixj]=t1;
                    }
                }
            }
            __syncthreads();
        }
    }

    for (int e=tid;e<2048;e+=1024){
        float kv = skey[e];
        float vv = -kv;
        float Ejv = __expf(vv);
        float Fjv = __expf(0.01f*vv);
        g_key [b*Nn+e]=kv;  g_perm[b*Nn+e]=sidx[e];
        g_Ej  [b*Nn+e]=Ejv; g_Fj  [b*Nn+e]=Fjv;
        sa[e]=Ejv; sb[e]=Fjv;
    }
    __syncthreads();

    // inclusive Hillis-Steele scan of sa (ping-pong with st)
    {
        float* src = sa; float* dst = st;
        for (int d=1; d<2048; d<<=1){
            for (int e=tid;e<2048;e+=1024)
                dst[e] = src[e] + (e>=d ? src[e-d] : 0.f);
            __syncthreads();
            float* tp=src; src=dst; dst=tp;
        }
        for (int e=tid;e<2048;e+=1024) g_PzE[b*Nn+e] = src[e];
        __syncthreads();
    }
    // scan of sb (ping-pong with sa, now free)
    {
        float* src = sb; float* dst = sa;
        for (int d=1; d<2048; d<<=1){
            for (int e=tid;e<2048;e+=1024)
                dst[e] = src[e] + (e>=d ? src[e-d] : 0.f);
            __syncthreads();
            float* tp=src; src=dst; dst=tp;
        }
        for (int e=tid;e<2048;e+=1024) g_PzF[b*Nn+e] = src[e];
    }
}

// ============ Kernel C1: chunk-local vector prefixes of Ej*Wh, Fj*Wh ==========
__global__ void prefix_chunks() {
    __shared__ int   sperm[CSZ];
    __shared__ float sE[CSZ], sF[CSZ];
    int b = blockIdx.y, ch = blockIdx.x, f = threadIdx.x; // 128 thr
    int base = ch*CSZ;
    if (f < CSZ){
        sperm[f]=g_perm[b*Nn+base+f];
        sE[f]=g_Ej[b*Nn+base+f];
        sF[f]=g_Fj[b*Nn+base+f];
    }
    __syncthreads();
    float ae=0.f, af=0.f;
    #pragma unroll 4
    for (int m=0;m<CSZ;m++){
        int j = sperm[m];
        float w = g_Wh[((size_t)b*Nn + j)*Ff + f];
        ae = fmaf(sE[m], w, ae);
        af = fmaf(sF[m], w, af);
        size_t o = ((size_t)b*Nn + base + m)*Ff + f;
        g_PE[o]=ae; g_PF[o]=af;
    }
    g_chE[(b*NCH+ch)*Ff+f]=ae;
    g_chF[(b*NCH+ch)*Ff+f]=af;
}

// ================= Kernel C2: exclusive scan of chunk totals ==================
__global__ void scan_chunks(){
    int b=blockIdx.x, f=threadIdx.x; // 128 thr
    float se=0.f, sf=0.f;
    for (int c=0;c<NCH;c++){
        g_offE[(b*NCH+c)*Ff+f]=se;
        g_offF[(b*NCH+c)*Ff+f]=sf;
        se += g_chE[(b*NCH+c)*Ff+f];
        sf += g_chF[(b*NCH+c)*Ff+f];
    }
    g_TF[b*Ff+f]=sf;
}

// ================= Kernel D: binary search + combine ==========================
__global__ void finalize(float* __restrict__ out){
    __shared__ float skey[2048];
    int b  = blockIdx.y;
    int tx = threadIdx.x;  // 128 (feature)
    int ty = threadIdx.y;  // 8 rows per block
    int t  = ty*128+tx;
    for (int e=t; e<2048; e+=1024) skey[e]=g_key[b*Nn+e];
    __syncthreads();

    int row = blockIdx.x*8 + ty;
    float uu = g_u[b*Nn+row];
    int lo=0, hi=2048;
    while (lo<hi){ int mid=(lo+hi)>>1; if (skey[mid] < uu) lo=mid+1; else hi=mid; }
    int k = lo;  // count of v_j > -u_i  (E-branch prefix length)

    float Ei = __expf(uu), Fi = __expf(0.01f*uu);
    float TFf = g_TF[b*Ff+tx];
    float TzF = g_PzF[b*Nn + 2047];

    float pe=0.f, pf=0.f, pze=0.f, pzf=0.f;
    if (k>0){
        int km = k-1, c = km>>6; // /CSZ
        size_t o = ((size_t)b*Nn+km)*Ff+tx;
        pe  = g_PE[o] + g_offE[(b*NCH+c)*Ff+tx];
        pf  = g_PF[o] + g_offF[(b*NCH+c)*Ff+tx];
        pze = g_PzE[b*Nn+km];
        pzf = g_PzF[b*Nn+km];
    }
    float num = Ei*pe + Fi*(TFf - pf);
    float den = Ei*pze + Fi*(TzF - pzf);
    out[((size_t)b*Nn+row)*Ff+tx] = num/den;
}

// ================= launch =================
extern "C" void kernel_launch(void* const* d_in, const int* in_sizes, int n_in,
                              void* d_out, int out_size) {
    const float* h  = (const float*)d_in[0];
    const float* W  = (const float*)d_in[1];
    const float* ai = (const float*)d_in[2];
    const float* aj = (const float*)d_in[3];
    float* out = (float*)d_out;

    gemm_uv     <<<dim3(Nn/64, Bb), dim3(32,8)>>>(h, W, ai, aj);
    sort_scan   <<<Bb, 1024>>>();
    prefix_chunks<<<dim3(NCH, Bb), 128>>>();
    scan_chunks <<<Bb, 128>>>();
    finalize    <<<dim3(Nn/8, Bb), dim3(128,8)>>>(out);
}